// round 2
// baseline (speedup 1.0000x reference)
#include <cuda_runtime.h>
#include <math.h>

typedef unsigned long long ull;

#define NBATCH 2048

// ---------------- device scratch (sanctioned: __device__ globals) ----------------
__device__ __align__(16) float2 g_W2p[2700];                      // composed 5x5 weights, duplicated pairs
__device__ float g_b2[18];                                        // composed bias
__device__ __align__(16) float g_pool1[(size_t)NBATCH * 18 * 30 * 30]; // 132.7 MB
__device__ __align__(16) float g_feat[(size_t)NBATCH * 3042];          // 24.9 MB
__device__ __align__(16) float g_l1t[3044 * 64];                  // l1_w transposed
__device__ __align__(16) float g_l2t[64 * 64];                    // l2_w transposed

// ---------------- packed f32x2 helpers ----------------
__device__ __forceinline__ void ffma2(ull& d, ull a, ull b) {
    asm("fma.rn.f32x2 %0, %1, %2, %0;" : "+l"(d) : "l"(a), "l"(b));
}
__device__ __forceinline__ ull pk2(float lo, float hi) {
    ull r;
    asm("mov.b64 %0, {%1, %2};" : "=l"(r) : "f"(lo), "f"(hi));
    return r;
}
__device__ __forceinline__ float2 upk2(ull v) {
    float2 r;
    asm("mov.b64 {%0, %1}, %2;" : "=f"(r.x), "=f"(r.y) : "l"(v));
    return r;
}

// ---------------- kernel: compose conv1*conv2 -> 5x5, and transpose MLP weights ----------------
__global__ void k_compose(const float* __restrict__ c1w, const float* __restrict__ c1b,
                          const float* __restrict__ c2w, const float* __restrict__ c2b) {
    int idx = blockIdx.x * blockDim.x + threadIdx.x;
    if (idx < 2700) {
        int o = idx / 150;
        int ci = (idx / 25) % 6;
        int y = (idx % 25) / 5;
        int x = idx % 5;
        int ky_lo = y > 2 ? y - 2 : 0, ky_hi = y < 2 ? y : 2;
        int kx_lo = x > 2 ? x - 2 : 0, kx_hi = x < 2 ? x : 2;
        float s = 0.f;
        for (int m = 0; m < 18; m++)
            for (int ky = ky_lo; ky <= ky_hi; ky++)
                for (int kx = kx_lo; kx <= kx_hi; kx++)
                    s += c1w[((m * 6 + ci) * 3 + ky) * 3 + kx] *
                         c2w[((o * 18 + m) * 3 + (y - ky)) * 3 + (x - kx)];
        g_W2p[idx] = make_float2(s, s);
    } else if (idx < 2718) {
        int o = idx - 2700;
        float s = c2b[o];
        for (int m = 0; m < 18; m++) {
            float t = 0.f;
            for (int q = 0; q < 9; q++) t += c2w[(o * 18 + m) * 9 + q];
            s += c1b[m] * t;
        }
        g_b2[o] = s;
    }
}

__global__ void k_prep(const float* __restrict__ l1w, const float* __restrict__ l2w) {
    int idx = blockIdx.x * blockDim.x + threadIdx.x;
    if (idx < 194816) {
        int o = idx & 63, k = idx >> 6;
        g_l1t[idx] = l1w[o * 3044 + k];
    } else if (idx < 198912) {
        int j = idx - 194816;
        int o = j & 63, k = j >> 6;
        g_l2t[j] = l2w[o * 64 + k];
    }
}

// ---------------- kernel: composed 5x5 conv (6->18) + maxpool2, 2 samples/CTA ----------------
// smem: W2ps (2700 ull = 21600B) + b2s (pad to 96B) + inS 2*6*64*64 f32 (196608B) = 218304B
#define SMEM_A 218304

__global__ __launch_bounds__(512, 1) void k_convA(const float* __restrict__ states) {
    extern __shared__ char smA[];
    ull* W2ps = (ull*)smA;
    float* b2s = (float*)(smA + 21600);
    float* inS = (float*)(smA + 21696);
    const int tid = threadIdx.x;

    for (int i = tid; i < 2700; i += 512) W2ps[i] = ((const ull*)g_W2p)[i];
    if (tid < 18) b2s[tid] = g_b2[tid];

    const int b0 = blockIdx.x * 2;
    {
        const float4* src = (const float4*)(states + (size_t)b0 * 24576);
        float4* dst = (float4*)inS;
        for (int i = tid; i < 12288; i += 512) dst[i] = src[i];
    }
    __syncthreads();

    // strip: (sample, oc-pair, pooled row, pooled col-block of 6)
    for (int t = tid; t < 2700; t += 512) {
        int s = t / 1350;
        int r2 = t - s * 1350;
        int ocp = r2 / 150;
        int rem = r2 - ocp * 150;
        int prow = rem / 5;
        int pblk = rem - prow * 5;

        ull acc[2][2][6];
#pragma unroll
        for (int a = 0; a < 2; a++)
#pragma unroll
            for (int r = 0; r < 2; r++)
#pragma unroll
                for (int j = 0; j < 6; j++) acc[a][r][j] = 0ull;

#pragma unroll 1
        for (int ci = 0; ci < 6; ci++) {
            const float* rbase = inS + ((s * 6 + ci) << 12) + (2 * prow) * 64 + pblk * 12;
#pragma unroll
            for (int iy = 0; iy < 6; iy++) {
                const ull* vp = (const ull*)(rbase + (iy << 6));
                ull ve[8];
#pragma unroll
                for (int j = 0; j < 8; j++) ve[j] = vp[j];
                ull vo[7];
#pragma unroll
                for (int j = 0; j < 7; j++) vo[j] = pk2(upk2(ve[j]).y, upk2(ve[j + 1]).x);
#pragma unroll
                for (int r = 0; r < 2; r++) {
                    int ky = iy - r;
                    if (ky < 0 || ky > 4) continue;
#pragma unroll
                    for (int oc = 0; oc < 2; oc++) {
                        const ull* wb = W2ps + (ocp * 2 + oc) * 150 + ci * 25 + ky * 5;
                        ull w0 = wb[0], w1 = wb[1], w2 = wb[2], w3 = wb[3], w4 = wb[4];
#pragma unroll
                        for (int j = 0; j < 6; j++) {
                            ffma2(acc[oc][r][j], w0, ve[j]);
                            ffma2(acc[oc][r][j], w1, vo[j]);
                            ffma2(acc[oc][r][j], w2, ve[j + 1]);
                            ffma2(acc[oc][r][j], w3, vo[j + 1]);
                            ffma2(acc[oc][r][j], w4, ve[j + 2]);
                        }
                    }
                }
            }
        }
#pragma unroll
        for (int oc = 0; oc < 2; oc++) {
            int ocg = ocp * 2 + oc;
            float bias = b2s[ocg];
            float* op = g_pool1 + ((((size_t)(b0 + s) * 18 + ocg) * 30 + prow) * 30 + pblk * 6);
#pragma unroll
            for (int j = 0; j < 6; j++) {
                float2 a0 = upk2(acc[oc][0][j]);
                float2 a1 = upk2(acc[oc][1][j]);
                op[j] = fmaxf(fmaxf(a0.x, a0.y), fmaxf(a1.x, a1.y)) + bias;
            }
        }
    }
}

// ---------------- convB helper: accumulate one ci of a 3x3 conv over a 2-row x NP-pair strip ----------------
template <int NP>
__device__ __forceinline__ void conv3_ci(const float* rb, int rstride, const ull* wb,
                                         ull (&acc)[2][7]) {
#pragma unroll
    for (int iy = 0; iy < 4; iy++) {
        const ull* vp = (const ull*)(rb + iy * rstride);
        ull ve[NP + 1];
#pragma unroll
        for (int j = 0; j < NP + 1; j++) ve[j] = vp[j];
        ull vo[NP];
#pragma unroll
        for (int j = 0; j < NP; j++) vo[j] = pk2(upk2(ve[j]).y, upk2(ve[j + 1]).x);
#pragma unroll
        for (int r = 0; r < 2; r++) {
            int ky = iy - r;
            if (ky < 0 || ky > 2) continue;
            ull w0 = wb[ky * 3], w1 = wb[ky * 3 + 1], w2 = wb[ky * 3 + 2];
#pragma unroll
            for (int j = 0; j < NP; j++) {
                ffma2(acc[r][j], w0, ve[j]);
                ffma2(acc[r][j], w1, vo[j]);
                ffma2(acc[r][j], w2, ve[j + 1]);
            }
        }
    }
}

// ---------------- kernel: conv3 -> conv4 -> avgpool -> flatten, 1 sample/CTA ----------------
// smem layout (bytes): w3p[2916]ull @0, w4p @23328, b3 @46656, b4 @46728, pS @46800 (64800B), zS @111600 (56448B)
#define SMEM_B 168048

__global__ __launch_bounds__(512, 1) void k_convB(const float* __restrict__ c3w, const float* __restrict__ c3b,
                                                  const float* __restrict__ c4w, const float* __restrict__ c4b) {
    extern __shared__ char smB[];
    ull* w3p = (ull*)smB;
    ull* w4p = (ull*)(smB + 23328);
    float* b3s = (float*)(smB + 46656);
    float* b4s = (float*)(smB + 46728);
    float* pS = (float*)(smB + 46800);
    float* zS = (float*)(smB + 111600);
    const int tid = threadIdx.x;
    const size_t samp = blockIdx.x;

    for (int i = tid; i < 2916; i += 512) {
        float a = c3w[i], b = c4w[i];
        w3p[i] = pk2(a, a);
        w4p[i] = pk2(b, b);
    }
    if (tid < 18) { b3s[tid] = c3b[tid]; b4s[tid] = c4b[tid]; }
    {
        const float4* src = (const float4*)(g_pool1 + samp * 16200);
        float4* dst = (float4*)pS;
        for (int i = tid; i < 4050; i += 512) dst[i] = src[i];
    }
    __syncthreads();

    // stage 1: conv3 (18->18, 30x30 -> 28x28), strips: oc(18) x rowpair(14) x colhalf(2) = 504
    if (tid < 504) {
        int oc = tid / 28;
        int rem = tid - oc * 28;
        int rowp = rem >> 1;
        int ch = rem & 1;
        int c0 = ch * 14;
        ull acc[2][7];
#pragma unroll
        for (int r = 0; r < 2; r++)
#pragma unroll
            for (int j = 0; j < 7; j++) acc[r][j] = 0ull;
#pragma unroll 1
        for (int ci = 0; ci < 18; ci++)
            conv3_ci<7>(pS + (ci * 30 + 2 * rowp) * 30 + c0, 30, w3p + oc * 162 + ci * 9, acc);
        float b = b3s[oc];
#pragma unroll
        for (int r = 0; r < 2; r++) {
            int row = 2 * rowp + r;
            float2* zp = (float2*)(zS + (oc * 28 + row) * 28 + c0);
#pragma unroll
            for (int j = 0; j < 7; j++) {
                float2 v = upk2(acc[r][j]);
                zp[j] = make_float2(v.x + b, v.y + b);
            }
        }
    }
    __syncthreads();

    // stage 2: conv4 (18->18, 28x28 -> 26x26) + avgpool -> 13x13
    // strips: oc(18) x pooled row(13) x colhalf(2) = 468 (ch0: 7 pairs, ch1: 6 pairs)
    if (tid < 468) {
        int oc = tid / 26;
        int rem = tid - oc * 26;
        int prow = rem >> 1;
        int ch = rem & 1;
        int c0 = ch * 14;
        ull acc[2][7];
#pragma unroll
        for (int r = 0; r < 2; r++)
#pragma unroll
            for (int j = 0; j < 7; j++) acc[r][j] = 0ull;
        if (ch == 0) {
#pragma unroll 1
            for (int ci = 0; ci < 18; ci++)
                conv3_ci<7>(zS + (ci * 28 + 2 * prow) * 28 + c0, 28, w4p + oc * 162 + ci * 9, acc);
        } else {
#pragma unroll 1
            for (int ci = 0; ci < 18; ci++)
                conv3_ci<6>(zS + (ci * 28 + 2 * prow) * 28 + c0, 28, w4p + oc * 162 + ci * 9, acc);
        }
        int np = ch ? 6 : 7;
        float b = b4s[oc];
        float* fo = g_feat + samp * 3042 + (oc * 13 + prow) * 13 + ch * 7;
        for (int j = 0; j < np; j++) {
            float2 a0 = upk2(acc[0][j]);
            float2 a1 = upk2(acc[1][j]);
            fo[j] = 0.25f * (a0.x + a0.y + a1.x + a1.y) + b;
        }
    }
}

// ---------------- kernel: MLP + expert routing + softmax, 8 samples/CTA ----------------
#define SMEM_M 101760

__global__ __launch_bounds__(512, 1) void k_mlp(const float* __restrict__ scores, const float* __restrict__ times,
                                                const int* __restrict__ agents,
                                                const float* __restrict__ l1b, const float* __restrict__ l2b,
                                                const float* __restrict__ agw, const float* __restrict__ agb,
                                                float* __restrict__ out) {
    extern __shared__ float smM[];
    float* featS = smM;                // 8 * 3044
    float* h1S = featS + 8 * 3044;     // 512
    float* h2S = h1S + 512;            // 512
    float* logS = h2S + 512;           // 64
    const int tid = threadIdx.x;
    const int sb = blockIdx.x * 8;

    for (int i = tid; i < 8 * 1521; i += 512) {
        int s = i / 1521;
        int r = i - s * 1521;
        ((float2*)(featS + s * 3044))[r] = ((const float2*)(g_feat + (size_t)(sb + s) * 3042))[r];
    }
    if (tid < 8) {
        featS[tid * 3044 + 3042] = scores[sb + tid];
        featS[tid * 3044 + 3043] = times[sb + tid];
    }
    __syncthreads();

    const int s = tid >> 6, o = tid & 63;
    {
        const float* f = featS + s * 3044;
        float a = 0.f;
#pragma unroll 4
        for (int k = 0; k < 3044; k++) a += f[k] * g_l1t[k * 64 + o];
        h1S[tid] = tanhf(a + l1b[o]);
    }
    __syncthreads();
    {
        const float* h = h1S + s * 64;
        float a = 0.f;
#pragma unroll
        for (int k = 0; k < 64; k++) a += h[k] * g_l2t[k * 64 + o];
        h2S[tid] = tanhf(a + l2b[o]);
    }
    __syncthreads();
    if (tid < 40) {
        int ss = tid / 5, oo = tid - ss * 5;
        int ag = agents[sb + ss];
        const float* W = agw + (ag * 5 + oo) * 64;
        const float* h = h2S + ss * 64;
        float a = agb[ag * 5 + oo];
#pragma unroll
        for (int k = 0; k < 64; k++) a += W[k] * h[k];
        logS[ss * 8 + oo] = a;
    }
    __syncthreads();
    if (tid < 8) {
        float m = -1e30f;
        for (int i = 0; i < 5; i++) m = fmaxf(m, logS[tid * 8 + i]);
        float e[5], sum = 0.f;
        for (int i = 0; i < 5; i++) { e[i] = expf(logS[tid * 8 + i] - m); sum += e[i]; }
        float inv = 1.f / sum;
        for (int i = 0; i < 5; i++) out[(sb + tid) * 5 + i] = e[i] * inv;
    }
}

// ---------------- launch ----------------
extern "C" void kernel_launch(void* const* d_in, const int* in_sizes, int n_in,
                              void* d_out, int out_size) {
    const float* states = (const float*)d_in[0];
    const float* scores = (const float*)d_in[1];
    const float* times  = (const float*)d_in[2];
    const int*   agents = (const int*)d_in[3];
    const float* c1w = (const float*)d_in[4];
    const float* c1b = (const float*)d_in[5];
    const float* c2w = (const float*)d_in[6];
    const float* c2b = (const float*)d_in[7];
    const float* c3w = (const float*)d_in[8];
    const float* c3b = (const float*)d_in[9];
    const float* c4w = (const float*)d_in[10];
    const float* c4b = (const float*)d_in[11];
    const float* l1w = (const float*)d_in[12];
    const float* l1b = (const float*)d_in[13];
    const float* l2w = (const float*)d_in[14];
    const float* l2b = (const float*)d_in[15];
    const float* agw = (const float*)d_in[16];
    const float* agb = (const float*)d_in[17];
    float* out = (float*)d_out;

    cudaFuncSetAttribute(k_convA, cudaFuncAttributeMaxDynamicSharedMemorySize, SMEM_A);
    cudaFuncSetAttribute(k_convB, cudaFuncAttributeMaxDynamicSharedMemorySize, SMEM_B);
    cudaFuncSetAttribute(k_mlp, cudaFuncAttributeMaxDynamicSharedMemorySize, SMEM_M);

    k_compose<<<3, 1024>>>(c1w, c1b, c2w, c2b);
    k_prep<<<389, 512>>>(l1w, l2w);
    k_convA<<<1024, 512, SMEM_A>>>(states);
    k_convB<<<2048, 512, SMEM_B>>>(c3w, c3b, c4w, c4b);
    k_mlp<<<256, 512, SMEM_M>>>(scores, times, agents, l1b, l2b, agw, agb, out);
}

// round 3
// speedup vs baseline: 1.2907x; 1.2907x over previous
#include <cuda_runtime.h>
#include <math.h>

typedef unsigned long long ull;

#define NBATCH 2048
#define NPAIR 1024

// ---------------- device scratch ----------------
__device__ __align__(16) float2 g_W2p[2700];                         // composed 5x5 weights, (w,w) pairs
__device__ float g_b2[18];
__device__ __align__(16) ull g_pool1p[(size_t)NPAIR * 18 * 30 * 30]; // pool1, sample-pair interleaved (132.7MB)
__device__ __align__(16) ull g_zp[(size_t)NPAIR * 18 * 28 * 28];     // conv3 out, interleaved (115.6MB)
__device__ __align__(16) float g_feat[(size_t)NBATCH * 3042];        // flattened features (24.9MB)
__device__ __align__(16) float g_l1t[3044 * 64];                     // l1_w transposed
__device__ __align__(16) float g_l2t[64 * 64];                       // l2_w transposed

// ---------------- packed f32x2 helpers ----------------
__device__ __forceinline__ void ffma2(ull& d, ull a, ull b) {
    asm("fma.rn.f32x2 %0, %1, %2, %0;" : "+l"(d) : "l"(a), "l"(b));
}
__device__ __forceinline__ ull pk2(float lo, float hi) {
    ull r;
    asm("mov.b64 %0, {%1, %2};" : "=l"(r) : "f"(lo), "f"(hi));
    return r;
}
__device__ __forceinline__ float2 upk2(ull v) {
    float2 r;
    asm("mov.b64 {%0, %1}, %2;" : "=f"(r.x), "=f"(r.y) : "l"(v));
    return r;
}

// ---------------- compose conv1*conv2 -> one 5x5 conv ----------------
__global__ void k_compose(const float* __restrict__ c1w, const float* __restrict__ c1b,
                          const float* __restrict__ c2w, const float* __restrict__ c2b) {
    int idx = blockIdx.x * blockDim.x + threadIdx.x;
    if (idx < 2700) {
        int o = idx / 150;
        int ci = (idx / 25) % 6;
        int y = (idx % 25) / 5;
        int x = idx % 5;
        int ky_lo = y > 2 ? y - 2 : 0, ky_hi = y < 2 ? y : 2;
        int kx_lo = x > 2 ? x - 2 : 0, kx_hi = x < 2 ? x : 2;
        float s = 0.f;
        for (int m = 0; m < 18; m++)
            for (int ky = ky_lo; ky <= ky_hi; ky++)
                for (int kx = kx_lo; kx <= kx_hi; kx++)
                    s += c1w[((m * 6 + ci) * 3 + ky) * 3 + kx] *
                         c2w[((o * 18 + m) * 3 + (y - ky)) * 3 + (x - kx)];
        g_W2p[idx] = make_float2(s, s);
    } else if (idx < 2718) {
        int o = idx - 2700;
        float s = c2b[o];
        for (int m = 0; m < 18; m++) {
            float t = 0.f;
            for (int q = 0; q < 9; q++) t += c2w[(o * 18 + m) * 9 + q];
            s += c1b[m] * t;
        }
        g_b2[o] = s;
    }
}

__global__ void k_prep(const float* __restrict__ l1w, const float* __restrict__ l2w) {
    int idx = blockIdx.x * blockDim.x + threadIdx.x;
    if (idx < 194816) {
        int o = idx & 63, k = idx >> 6;
        g_l1t[idx] = l1w[o * 3044 + k];
    } else if (idx < 198912) {
        int j = idx - 194816;
        int o = j & 63, k = j >> 6;
        g_l2t[j] = l2w[o * 64 + k];
    }
}

// ---------------- convA: composed 5x5 (6->18) + maxpool2, sample-pair per CTA ----------------
// smem: W2ps 21600B | b2s 96B | inP 6*64*64 ull = 196608B  => 218304B
#define SMEM_A 218304

__global__ __launch_bounds__(512, 1) void k_convA(const float* __restrict__ states) {
    extern __shared__ char smA[];
    ull* W2ps = (ull*)smA;
    float* b2s = (float*)(smA + 21600);
    ull* inP = (ull*)(smA + 21696);
    const int tid = threadIdx.x;

    for (int i = tid; i < 2700; i += 512) W2ps[i] = ((const ull*)g_W2p)[i];
    if (tid < 18) b2s[tid] = g_b2[tid];
    {
        const float4* s0 = (const float4*)(states + (size_t)blockIdx.x * 49152);
        const float4* s1 = s0 + 6144;
        float4* dst = (float4*)inP;
        for (int i = tid; i < 6144; i += 512) {
            float4 a = s0[i], b = s1[i];
            dst[2 * i] = make_float4(a.x, b.x, a.y, b.y);
            dst[2 * i + 1] = make_float4(a.z, b.z, a.w, b.w);
        }
    }
    __syncthreads();

    // strips: prow(30) x blk(6) x oc(18); oc fastest => data LDS fully broadcast within warp
    for (int t = tid; t < 3240; t += 512) {
        int oc = t % 18;
        int r2 = t / 18;
        int blk = r2 % 6;
        int prow = r2 / 6;
        int c0 = blk * 10;

        ull acc[2][10];
#pragma unroll
        for (int r = 0; r < 2; r++)
#pragma unroll
            for (int j = 0; j < 10; j++) acc[r][j] = 0ull;

        const ull* wb = W2ps + oc * 150;
#pragma unroll 1
        for (int ci = 0; ci < 6; ci++) {
            const ull* rb = inP + (ci << 12) + (prow << 7) + c0;
            const ull* wc = wb + ci * 25;
            ull wn[5], wp[5];
#pragma unroll
            for (int iy = 0; iy < 6; iy++) {
                ull v[14];
                {
                    const ulonglong2* vp = (const ulonglong2*)(rb + (iy << 6));
#pragma unroll
                    for (int j = 0; j < 7; j++) { ulonglong2 q = vp[j]; v[2 * j] = q.x; v[2 * j + 1] = q.y; }
                }
                if (iy < 5) {
#pragma unroll
                    for (int q = 0; q < 5; q++) wn[q] = wc[iy * 5 + q];
#pragma unroll
                    for (int kx = 0; kx < 5; kx++)
#pragma unroll
                        for (int j = 0; j < 10; j++) ffma2(acc[0][j], wn[kx], v[j + kx]);
                }
                if (iy >= 1) {
#pragma unroll
                    for (int kx = 0; kx < 5; kx++)
#pragma unroll
                        for (int j = 0; j < 10; j++) ffma2(acc[1][j], wp[kx], v[j + kx]);
                }
#pragma unroll
                for (int q = 0; q < 5; q++) wp[q] = wn[q];
            }
        }
        float bias = b2s[oc];
        ull* op = g_pool1p + (((size_t)blockIdx.x * 18 + oc) * 30 + prow) * 30 + blk * 5;
#pragma unroll
        for (int p = 0; p < 5; p++) {
            float2 a0 = upk2(acc[0][2 * p]), a1 = upk2(acc[0][2 * p + 1]);
            float2 b0 = upk2(acc[1][2 * p]), b1 = upk2(acc[1][2 * p + 1]);
            float2 m;
            m.x = fmaxf(fmaxf(a0.x, a1.x), fmaxf(b0.x, b1.x)) + bias;
            m.y = fmaxf(fmaxf(a0.y, a1.y), fmaxf(b0.y, b1.y)) + bias;
            ((float2*)op)[p] = m;
        }
    }
}

// ---------------- shared 3x3 pair-conv strip (rolling weight rows) ----------------
template <int COLS>
__device__ __forceinline__ void conv3x3_pair(const ull* rb, int rstride, const ull* wc,
                                             ull (&acc)[2][COLS]) {
    ull wn[3], wp[3];
#pragma unroll
    for (int iy = 0; iy < 4; iy++) {
        ull v[COLS + 2];
        {
            const ulonglong2* vp = (const ulonglong2*)(rb + iy * rstride);
#pragma unroll
            for (int j = 0; j < (COLS + 2) / 2; j++) { ulonglong2 q = vp[j]; v[2 * j] = q.x; v[2 * j + 1] = q.y; }
        }
        if (iy < 3) {
            wn[0] = wc[iy * 3]; wn[1] = wc[iy * 3 + 1]; wn[2] = wc[iy * 3 + 2];
#pragma unroll
            for (int kx = 0; kx < 3; kx++)
#pragma unroll
                for (int j = 0; j < COLS; j++) ffma2(acc[0][j], wn[kx], v[j + kx]);
        }
        if (iy >= 1) {
#pragma unroll
            for (int kx = 0; kx < 3; kx++)
#pragma unroll
                for (int j = 0; j < COLS; j++) ffma2(acc[1][j], wp[kx], v[j + kx]);
        }
        wp[0] = wn[0]; wp[1] = wn[1]; wp[2] = wn[2];
    }
}

// ---------------- conv3: 18->18, 30x30 -> 28x28, pair per CTA ----------------
// smem: w3p 23328B | b3 96B | pS 18*30*32 ull = 138240B  => 161664B
#define SMEM_C3 161664

__global__ __launch_bounds__(512, 1) void k_conv3(const float* __restrict__ c3w, const float* __restrict__ c3b) {
    extern __shared__ char smC[];
    ull* w3p = (ull*)smC;
    float* b3s = (float*)(smC + 23328);
    ull* pS = (ull*)(smC + 23424);  // row stride 32 ull (16B-aligned rows)
    const int tid = threadIdx.x;

    for (int i = tid; i < 2916; i += 512) { float w = c3w[i]; w3p[i] = pk2(w, w); }
    if (tid < 18) b3s[tid] = c3b[tid];
    {
        const ull* src = g_pool1p + (size_t)blockIdx.x * 16200;
        for (int e = tid; e < 16200; e += 512) {
            int c = e % 30;
            int rr = (e / 30) % 30;
            int ci = e / 900;
            pS[ci * 960 + rr * 32 + c] = src[e];
        }
    }
    __syncthreads();

    // strips: rowp(14) x ch(2) x oc(18) = 504; oc fastest
    if (tid < 504) {
        int oc = tid % 18;
        int r2 = tid / 18;
        int ch = r2 % 2;
        int rowp = r2 / 2;
        int c0 = ch * 14;

        ull acc[2][14];
#pragma unroll
        for (int r = 0; r < 2; r++)
#pragma unroll
            for (int j = 0; j < 14; j++) acc[r][j] = 0ull;

#pragma unroll 1
        for (int ci = 0; ci < 18; ci++)
            conv3x3_pair<14>(pS + ci * 960 + rowp * 64 + c0, 32, w3p + (oc * 18 + ci) * 9, acc);

        float b = b3s[oc];
        ull* zb = g_zp + (((size_t)blockIdx.x * 18 + oc) * 28 + 2 * rowp) * 28 + c0;
#pragma unroll
        for (int r = 0; r < 2; r++)
#pragma unroll
            for (int j = 0; j < 14; j++) {
                float2 vv = upk2(acc[r][j]);
                ((float2*)zb)[r * 28 + j] = make_float2(vv.x + b, vv.y + b);
            }
    }
}

// ---------------- conv4: 18->18, 28x28 -> 26x26 + avgpool -> 13x13, pair per CTA ----------------
// smem: w4p 23328B | b4 96B | zS 18*784 ull = 112896B  => 136320B
#define SMEM_C4 136320

__global__ __launch_bounds__(512, 1) void k_conv4(const float* __restrict__ c4w, const float* __restrict__ c4b) {
    extern __shared__ char smD[];
    ull* w4p = (ull*)smD;
    float* b4s = (float*)(smD + 23328);
    ull* zS = (ull*)(smD + 23424);
    const int tid = threadIdx.x;

    for (int i = tid; i < 2916; i += 512) { float w = c4w[i]; w4p[i] = pk2(w, w); }
    if (tid < 18) b4s[tid] = c4b[tid];
    {
        const float4* src = (const float4*)(g_zp + (size_t)blockIdx.x * 14112);
        float4* dst = (float4*)zS;
        for (int i = tid; i < 7056; i += 512) dst[i] = src[i];
    }
    __syncthreads();

    // strips: prow(13) x ch(2) x oc(18) = 468; oc fastest; uniform COLS=14 (ch1 overlaps 2 cols)
    if (tid < 468) {
        int oc = tid % 18;
        int r2 = tid / 18;
        int ch = r2 % 2;
        int prow = r2 / 2;
        int c0 = ch * 12;  // ch0: cols 0..13, ch1: cols 12..25 (overlap, identical values)

        ull acc[2][14];
#pragma unroll
        for (int r = 0; r < 2; r++)
#pragma unroll
            for (int j = 0; j < 14; j++) acc[r][j] = 0ull;

#pragma unroll 1
        for (int ci = 0; ci < 18; ci++)
            conv3x3_pair<14>(zS + ci * 784 + 2 * prow * 28 + c0, 28, w4p + (oc * 18 + ci) * 9, acc);

        float b = b4s[oc];
        float* f0 = g_feat + (size_t)(2 * blockIdx.x) * 3042 + (oc * 13 + prow) * 13 + c0 / 2;
        float* f1 = f0 + 3042;
        int plo = ch ? 1 : 0;  // ch1 skips overlapped pooled col
#pragma unroll
        for (int p = 0; p < 7; p++) {
            if (p >= plo) {
                float2 a0 = upk2(acc[0][2 * p]), a1 = upk2(acc[0][2 * p + 1]);
                float2 b0 = upk2(acc[1][2 * p]), b1 = upk2(acc[1][2 * p + 1]);
                f0[p] = 0.25f * (a0.x + a1.x + b0.x + b1.x) + b;
                f1[p] = 0.25f * (a0.y + a1.y + b0.y + b1.y) + b;
            }
        }
    }
}

// ---------------- MLP + expert routing + softmax, 8 samples/CTA ----------------
#define SMEM_M 101760

__global__ __launch_bounds__(512, 1) void k_mlp(const float* __restrict__ scores, const float* __restrict__ times,
                                                const int* __restrict__ agents,
                                                const float* __restrict__ l1b, const float* __restrict__ l2b,
                                                const float* __restrict__ agw, const float* __restrict__ agb,
                                                float* __restrict__ out) {
    extern __shared__ float smM[];
    float* featS = smM;
    float* h1S = featS + 8 * 3044;
    float* h2S = h1S + 512;
    float* logS = h2S + 512;
    const int tid = threadIdx.x;
    const int sb = blockIdx.x * 8;

    for (int i = tid; i < 8 * 1521; i += 512) {
        int s = i / 1521;
        int r = i - s * 1521;
        ((float2*)(featS + s * 3044))[r] = ((const float2*)(g_feat + (size_t)(sb + s) * 3042))[r];
    }
    if (tid < 8) {
        featS[tid * 3044 + 3042] = scores[sb + tid];
        featS[tid * 3044 + 3043] = times[sb + tid];
    }
    __syncthreads();

    const int s = tid >> 6, o = tid & 63;
    {
        const float* f = featS + s * 3044;
        float a = 0.f;
#pragma unroll 4
        for (int k = 0; k < 3044; k++) a += f[k] * g_l1t[k * 64 + o];
        h1S[tid] = tanhf(a + l1b[o]);
    }
    __syncthreads();
    {
        const float* h = h1S + s * 64;
        float a = 0.f;
#pragma unroll
        for (int k = 0; k < 64; k++) a += h[k] * g_l2t[k * 64 + o];
        h2S[tid] = tanhf(a + l2b[o]);
    }
    __syncthreads();
    if (tid < 40) {
        int ss = tid / 5, oo = tid - ss * 5;
        int ag = agents[sb + ss];
        const float* W = agw + (ag * 5 + oo) * 64;
        const float* h = h2S + ss * 64;
        float a = agb[ag * 5 + oo];
#pragma unroll
        for (int k = 0; k < 64; k++) a += W[k] * h[k];
        logS[ss * 8 + oo] = a;
    }
    __syncthreads();
    if (tid < 8) {
        float m = -1e30f;
        for (int i = 0; i < 5; i++) m = fmaxf(m, logS[tid * 8 + i]);
        float e[5], sum = 0.f;
        for (int i = 0; i < 5; i++) { e[i] = expf(logS[tid * 8 + i] - m); sum += e[i]; }
        float inv = 1.f / sum;
        for (int i = 0; i < 5; i++) out[(sb + tid) * 5 + i] = e[i] * inv;
    }
}

// ---------------- launch ----------------
extern "C" void kernel_launch(void* const* d_in, const int* in_sizes, int n_in,
                              void* d_out, int out_size) {
    const float* states = (const float*)d_in[0];
    const float* scores = (const float*)d_in[1];
    const float* times  = (const float*)d_in[2];
    const int*   agents = (const int*)d_in[3];
    const float* c1w = (const float*)d_in[4];
    const float* c1b = (const float*)d_in[5];
    const float* c2w = (const float*)d_in[6];
    const float* c2b = (const float*)d_in[7];
    const float* c3w = (const float*)d_in[8];
    const float* c3b = (const float*)d_in[9];
    const float* c4w = (const float*)d_in[10];
    const float* c4b = (const float*)d_in[11];
    const float* l1w = (const float*)d_in[12];
    const float* l1b = (const float*)d_in[13];
    const float* l2w = (const float*)d_in[14];
    const float* l2b = (const float*)d_in[15];
    const float* agw = (const float*)d_in[16];
    const float* agb = (const float*)d_in[17];
    float* out = (float*)d_out;

    cudaFuncSetAttribute(k_convA, cudaFuncAttributeMaxDynamicSharedMemorySize, SMEM_A);
    cudaFuncSetAttribute(k_conv3, cudaFuncAttributeMaxDynamicSharedMemorySize, SMEM_C3);
    cudaFuncSetAttribute(k_conv4, cudaFuncAttributeMaxDynamicSharedMemorySize, SMEM_C4);
    cudaFuncSetAttribute(k_mlp, cudaFuncAttributeMaxDynamicSharedMemorySize, SMEM_M);

    k_compose<<<3, 1024>>>(c1w, c1b, c2w, c2b);
    k_prep<<<389, 512>>>(l1w, l2w);
    k_convA<<<1024, 512, SMEM_A>>>(states);
    k_conv3<<<1024, 512, SMEM_C3>>>(c3w, c3b);
    k_conv4<<<1024, 512, SMEM_C4>>>(c4w, c4b);
    k_mlp<<<256, 512, SMEM_M>>>(scores, times, agents, l1b, l2b, agw, agb, out);
}

// round 4
// speedup vs baseline: 1.5388x; 1.1922x over previous
#include <cuda_runtime.h>
#include <math.h>

typedef unsigned long long ull;

#define NBATCH 2048
#define NPAIR 1024

// ---------------- device scratch ----------------
__device__ __align__(16) float2 g_W2p[2700];                         // composed 5x5 weights, (w,w) pairs
__device__ float g_b2[18];
__device__ __align__(16) ull g_pool1p[(size_t)NPAIR * 18 * 30 * 30]; // pool1, sample-pair interleaved
__device__ __align__(16) ull g_zp[(size_t)NPAIR * 18 * 28 * 28];     // conv3 out, interleaved
__device__ __align__(16) float g_feat[(size_t)NBATCH * 3042];        // flattened features

// ---------------- packed f32x2 helpers ----------------
__device__ __forceinline__ void ffma2(ull& d, ull a, ull b) {
    asm("fma.rn.f32x2 %0, %1, %2, %0;" : "+l"(d) : "l"(a), "l"(b));
}
__device__ __forceinline__ ull pk2(float lo, float hi) {
    ull r;
    asm("mov.b64 %0, {%1, %2};" : "=l"(r) : "f"(lo), "f"(hi));
    return r;
}
__device__ __forceinline__ float2 upk2(ull v) {
    float2 r;
    asm("mov.b64 {%0, %1}, %2;" : "=f"(r.x), "=f"(r.y) : "l"(v));
    return r;
}

// ---------------- compose conv1*conv2 -> one 5x5 conv ----------------
__global__ void k_compose(const float* __restrict__ c1w, const float* __restrict__ c1b,
                          const float* __restrict__ c2w, const float* __restrict__ c2b) {
    int idx = blockIdx.x * blockDim.x + threadIdx.x;
    if (idx < 2700) {
        int o = idx / 150;
        int ci = (idx / 25) % 6;
        int y = (idx % 25) / 5;
        int x = idx % 5;
        int ky_lo = y > 2 ? y - 2 : 0, ky_hi = y < 2 ? y : 2;
        int kx_lo = x > 2 ? x - 2 : 0, kx_hi = x < 2 ? x : 2;
        float s = 0.f;
        for (int m = 0; m < 18; m++)
            for (int ky = ky_lo; ky <= ky_hi; ky++)
                for (int kx = kx_lo; kx <= kx_hi; kx++)
                    s += c1w[((m * 6 + ci) * 3 + ky) * 3 + kx] *
                         c2w[((o * 18 + m) * 3 + (y - ky)) * 3 + (x - kx)];
        g_W2p[idx] = make_float2(s, s);
    } else if (idx < 2718) {
        int o = idx - 2700;
        float s = c2b[o];
        for (int m = 0; m < 18; m++) {
            float t = 0.f;
            for (int q = 0; q < 9; q++) t += c2w[(o * 18 + m) * 9 + q];
            s += c1b[m] * t;
        }
        g_b2[o] = s;
    }
}

// ---------------- convA: composed 5x5 (6->18) + maxpool2 ----------------
// grid (5 rowbands, 1024 pairs), 512 thr, 2 CTAs/SM
// smem: W2ps 21600 | b2s 96 | inP 6*16*64 ull = 49152  => 70848
#define SMEM_A 70848

__global__ __launch_bounds__(512, 2) void k_convA(const float* __restrict__ states) {
    extern __shared__ char smA[];
    ull* W2ps = (ull*)smA;
    float* b2s = (float*)(smA + 21600);
    ull* inP = (ull*)(smA + 21696);
    const int tid = threadIdx.x;
    const int band = blockIdx.x;       // 0..4, 6 pooled rows each
    const int pair = blockIdx.y;
    const int ir0 = 12 * band;         // first input row of this band (16 rows used)

    for (int i = tid; i < 2700; i += 512) W2ps[i] = ((const ull*)g_W2p)[i];
    if (tid < 18) b2s[tid] = g_b2[tid];
    {
        const float4* s0 = (const float4*)(states) + (size_t)pair * 12288;
        for (int i = tid; i < 1536; i += 512) {
            int c4 = i & 15, r = (i >> 4) & 15, ci = i >> 8;
            int goff = (ci * 64 + ir0 + r) * 16 + c4;
            float4 a = s0[goff], b = s0[goff + 6144];
            ulonglong2* d = (ulonglong2*)(inP + (ci << 10) + (r << 6) + (c4 << 2));
            ulonglong2 q0, q1;
            q0.x = pk2(a.x, b.x); q0.y = pk2(a.y, b.y);
            q1.x = pk2(a.z, b.z); q1.y = pk2(a.w, b.w);
            d[0] = q0; d[1] = q1;
        }
    }
    __syncthreads();

    // strips: pl(6) x blk(10) x oc(18) = 1080; oc fastest (warp-broadcast data LDS)
    for (int t = tid; t < 1080; t += 512) {
        int oc = t % 18;
        int r2 = t / 18;
        int blk = r2 % 10;
        int pl = r2 / 10;          // local pooled row 0..5
        int c0 = blk * 6;

        ull acc[2][6];
#pragma unroll
        for (int r = 0; r < 2; r++)
#pragma unroll
            for (int j = 0; j < 6; j++) acc[r][j] = 0ull;

#pragma unroll 1
        for (int ci = 0; ci < 6; ci++) {
            const ull* rb = inP + (ci << 10) + (pl << 7) + c0;   // 2*pl*64 = pl<<7
            const ull* wc = W2ps + oc * 150 + ci * 25;
#pragma unroll
            for (int iy = 0; iy < 6; iy++) {
                ull v[10];
                {
                    const ulonglong2* vp = (const ulonglong2*)(rb + (iy << 6));
#pragma unroll
                    for (int j = 0; j < 5; j++) { ulonglong2 q = vp[j]; v[2 * j] = q.x; v[2 * j + 1] = q.y; }
                }
                if (iy < 5) {
#pragma unroll
                    for (int kx = 0; kx < 5; kx++) {
                        ull w = wc[iy * 5 + kx];
#pragma unroll
                        for (int j = 0; j < 6; j++) ffma2(acc[0][j], w, v[j + kx]);
                    }
                }
                if (iy >= 1) {
#pragma unroll
                    for (int kx = 0; kx < 5; kx++) {
                        ull w = wc[(iy - 1) * 5 + kx];
#pragma unroll
                        for (int j = 0; j < 6; j++) ffma2(acc[1][j], w, v[j + kx]);
                    }
                }
            }
        }
        float bias = b2s[oc];
        int prow = band * 6 + pl;
        ull* op = g_pool1p + (((size_t)pair * 18 + oc) * 30 + prow) * 30 + blk * 3;
#pragma unroll
        for (int p = 0; p < 3; p++) {
            float2 a0 = upk2(acc[0][2 * p]), a1 = upk2(acc[0][2 * p + 1]);
            float2 b0 = upk2(acc[1][2 * p]), b1 = upk2(acc[1][2 * p + 1]);
            float2 m;
            m.x = fmaxf(fmaxf(a0.x, a1.x), fmaxf(b0.x, b1.x)) + bias;
            m.y = fmaxf(fmaxf(a0.y, a1.y), fmaxf(b0.y, b1.y)) + bias;
            ((float2*)op)[p] = m;
        }
    }
}

// ---------------- 3x3 pair-conv strip (rolling weight rows) ----------------
template <int COLS, bool ALIGNED>
__device__ __forceinline__ void conv3x3_pair(const ull* rb, int rstride, const ull* wc,
                                             ull (&acc)[2][COLS]) {
    ull wn0 = 0, wn1 = 0, wn2 = 0, wp0 = 0, wp1 = 0, wp2 = 0;
#pragma unroll
    for (int iy = 0; iy < 4; iy++) {
        ull v[COLS + 2];
        if (ALIGNED) {
            const ulonglong2* vp = (const ulonglong2*)(rb + iy * rstride);
#pragma unroll
            for (int j = 0; j < (COLS + 2) / 2; j++) { ulonglong2 q = vp[j]; v[2 * j] = q.x; v[2 * j + 1] = q.y; }
        } else {
#pragma unroll
            for (int j = 0; j < COLS + 2; j++) v[j] = rb[iy * rstride + j];
        }
        if (iy < 3) {
            wn0 = wc[iy * 3]; wn1 = wc[iy * 3 + 1]; wn2 = wc[iy * 3 + 2];
#pragma unroll
            for (int j = 0; j < COLS; j++) {
                ffma2(acc[0][j], wn0, v[j]);
                ffma2(acc[0][j], wn1, v[j + 1]);
                ffma2(acc[0][j], wn2, v[j + 2]);
            }
        }
        if (iy >= 1) {
#pragma unroll
            for (int j = 0; j < COLS; j++) {
                ffma2(acc[1][j], wp0, v[j]);
                ffma2(acc[1][j], wp1, v[j + 1]);
                ffma2(acc[1][j], wp2, v[j + 2]);
            }
        }
        wp0 = wn0; wp1 = wn1; wp2 = wn2;
    }
}

// ---------------- conv3: 18->18, 30x30 -> 28x28 ----------------
// grid (2 rowhalves, 1024 pairs), 512 thr, 2 CTAs/SM
// smem: w3p 23328 | b3 96 | pS 18*16*32 ull = 73728  => 97152
#define SMEM_C3 97152

__global__ __launch_bounds__(512, 2) void k_conv3(const float* __restrict__ c3w, const float* __restrict__ c3b) {
    extern __shared__ char smC[];
    ull* w3p = (ull*)smC;
    float* b3s = (float*)(smC + 23328);
    ull* pS = (ull*)(smC + 23424);
    const int tid = threadIdx.x;
    const int hf = blockIdx.x;         // 0: rowp 0..6, 1: rowp 7..13
    const int pair = blockIdx.y;
    const int ir0 = 14 * hf;

    for (int i = tid; i < 2916; i += 512) { float w = c3w[i]; w3p[i] = pk2(w, w); }
    if (tid < 18) b3s[tid] = c3b[tid];
    {
        const ull* src = g_pool1p + (size_t)pair * 16200;
        for (int e = tid; e < 8640; e += 512) {
            int c = e % 30;
            int r = (e / 30) & 15;
            int ci = e / 480;
            pS[ci * 512 + r * 32 + c] = src[(ci * 30 + ir0 + r) * 30 + c];
        }
    }
    __syncthreads();

    // strips: rl(7) x cq(4) x oc(18) = 504
    if (tid < 504) {
        int oc = tid % 18;
        int r2 = tid / 18;
        int cq = r2 % 4;
        int rl = r2 / 4;
        int c0 = cq * 7;

        ull acc[2][7];
#pragma unroll
        for (int r = 0; r < 2; r++)
#pragma unroll
            for (int j = 0; j < 7; j++) acc[r][j] = 0ull;

#pragma unroll 1
        for (int ci = 0; ci < 18; ci++)
            conv3x3_pair<7, false>(pS + ci * 512 + rl * 64 + c0, 32, w3p + (oc * 18 + ci) * 9, acc);

        float b = b3s[oc];
        int orow = 2 * (7 * hf + rl);
        ull* zb = g_zp + (((size_t)pair * 18 + oc) * 28 + orow) * 28 + c0;
#pragma unroll
        for (int r = 0; r < 2; r++)
#pragma unroll
            for (int j = 0; j < 7; j++) {
                float2 vv = upk2(acc[r][j]);
                ((float2*)zb)[r * 28 + j] = make_float2(vv.x + b, vv.y + b);
            }
    }
}

// ---------------- conv4: 18->18, 28x28 -> 26x26 + avgpool -> 13x13 ----------------
// grid (2 rowhalves, 1024 pairs), 512 thr, 2 CTAs/SM
// smem: w4p 23328 | b4 96 | zS 18*16*28 ull = 64512  => 87936
#define SMEM_C4 87936

__global__ __launch_bounds__(512, 2) void k_conv4(const float* __restrict__ c4w, const float* __restrict__ c4b) {
    extern __shared__ char smD[];
    ull* w4p = (ull*)smD;
    float* b4s = (float*)(smD + 23328);
    ull* zS = (ull*)(smD + 23424);
    const int tid = threadIdx.x;
    const int hf = blockIdx.x;         // 0: prow 0..6, 1: prow 7..12
    const int pair = blockIdx.y;
    const int ir0 = 14 * hf;
    const int nr = 16 - 2 * hf;        // rows loaded: 16 / 14

    for (int i = tid; i < 2916; i += 512) { float w = c4w[i]; w4p[i] = pk2(w, w); }
    if (tid < 18) b4s[tid] = c4b[tid];
    {
        int per_ci = nr * 14;  // ulonglong2 units per ci
        int total = 18 * per_ci;
        for (int i = tid; i < total; i += 512) {
            int ci = i / per_ci, rem = i - ci * per_ci;
            const ulonglong2* src = (const ulonglong2*)(g_zp + (size_t)pair * 14112 + ci * 784 + ir0 * 28);
            ((ulonglong2*)(zS + ci * 448))[rem] = src[rem];
        }
    }
    __syncthreads();

    // strips: rl(7 or 6) x cq(4) x oc(18); COLS=8 overlapping quarters (c0 = 6*cq)
    int nstrip = (hf ? 6 : 7) * 4 * 18;
    if (tid < nstrip) {
        int oc = tid % 18;
        int r2 = tid / 18;
        int cq = r2 % 4;
        int rl = r2 / 4;
        int c0 = cq * 6;

        ull acc[2][8];
#pragma unroll
        for (int r = 0; r < 2; r++)
#pragma unroll
            for (int j = 0; j < 8; j++) acc[r][j] = 0ull;

#pragma unroll 1
        for (int ci = 0; ci < 18; ci++)
            conv3x3_pair<8, true>(zS + ci * 448 + rl * 56 + c0, 28, w4p + (oc * 18 + ci) * 9, acc);

        float b = b4s[oc];
        int prow = 7 * hf + rl;
        float* f0 = g_feat + (size_t)(2 * pair) * 3042 + (oc * 13 + prow) * 13;
        float* f1 = f0 + 3042;
        int plo = cq ? 1 : 0;
#pragma unroll
        for (int pp = 0; pp < 4; pp++) {
            if (pp >= plo) {
                float2 a0 = upk2(acc[0][2 * pp]), a1 = upk2(acc[0][2 * pp + 1]);
                float2 b0 = upk2(acc[1][2 * pp]), b1 = upk2(acc[1][2 * pp + 1]);
                f0[3 * cq + pp] = 0.25f * (a0.x + a1.x + b0.x + b1.x) + b;
                f1[3 * cq + pp] = 0.25f * (a0.y + a1.y + b0.y + b1.y) + b;
            }
        }
    }
}

// ---------------- MLP + expert routing + softmax, 8 samples/CTA ----------------
// smem floats: featS 8*3076 | wT 64*132 | h1S 8*66 | h2S 512 | logS 64
#define SMEM_M ((8 * 3076 + 64 * 132 + 8 * 66 + 512 + 64) * 4)

__global__ __launch_bounds__(512, 1) void k_mlp(const float* __restrict__ scores, const float* __restrict__ times,
                                                const int* __restrict__ agents,
                                                const float* __restrict__ l1w, const float* __restrict__ l1b,
                                                const float* __restrict__ l2w, const float* __restrict__ l2b,
                                                const float* __restrict__ agw, const float* __restrict__ agb,
                                                float* __restrict__ out) {
    extern __shared__ float smM[];
    float* featS = smM;                       // stride 3076 per sample
    float* wT = featS + 8 * 3076;             // 64 x 132
    float* h1S = wT + 64 * 132;               // stride 66
    float* h2S = h1S + 8 * 66;                // stride 64
    float* logS = h2S + 512;
    const int tid = threadIdx.x;
    const int sb = blockIdx.x * 8;

    for (int i = tid; i < 8 * 1521; i += 512) {
        int s = i / 1521;
        int r = i - s * 1521;
        ((float2*)(featS + s * 3076))[r] = ((const float2*)(g_feat + (size_t)(sb + s) * 3042))[r];
    }
    if (tid < 8) {
        featS[tid * 3076 + 3042] = scores[sb + tid];
        featS[tid * 3076 + 3043] = times[sb + tid];
    }
    if (tid >= 32 && tid < 288) {
        int j = tid - 32;                     // zero-pad k = 3044..3075
        featS[(j >> 5) * 3076 + 3044 + (j & 31)] = 0.f;
    }
    __syncthreads();

    const int s = tid & 7, o = tid >> 3;      // o 0..63; 8 lanes per o broadcast
    ull f0a = 0, f1a = 0, f2a = 0, f3a = 0;
#pragma unroll 1
    for (int kt = 0; kt < 24; kt++) {
        int k0 = kt << 7;
        for (int i = tid; i < 8192; i += 512) {
            int oo = i >> 7, kk = i & 127;
            int k = k0 + kk;
            wT[oo * 132 + kk] = (k < 3044) ? l1w[oo * 3044 + k] : 0.f;
        }
        __syncthreads();
        const ull* fr = (const ull*)(featS + s * 3076 + k0);
        const ull* wr = (const ull*)(wT + o * 132);
#pragma unroll
        for (int kk = 0; kk < 64; kk += 4) {
            ffma2(f0a, fr[kk], wr[kk]);
            ffma2(f1a, fr[kk + 1], wr[kk + 1]);
            ffma2(f2a, fr[kk + 2], wr[kk + 2]);
            ffma2(f3a, fr[kk + 3], wr[kk + 3]);
        }
        __syncthreads();
    }
    {
        float2 a = upk2(f0a), b = upk2(f1a), c = upk2(f2a), d = upk2(f3a);
        float acc = (a.x + a.y) + (b.x + b.y) + (c.x + c.y) + (d.x + d.y);
        h1S[s * 66 + o] = tanhf(acc + l1b[o]);
    }
    __syncthreads();
    {
        const ull* hr = (const ull*)(h1S + s * 66);
        const ull* w2 = (const ull*)(l2w + o * 64);
        ull a0 = 0, a1 = 0;
#pragma unroll
        for (int kk = 0; kk < 32; kk += 2) {
            ffma2(a0, hr[kk], w2[kk]);
            ffma2(a1, hr[kk + 1], w2[kk + 1]);
        }
        float2 a = upk2(a0), b = upk2(a1);
        h2S[s * 64 + o] = tanhf(a.x + a.y + b.x + b.y + l2b[o]);
    }
    __syncthreads();
    if (tid < 40) {
        int ss = tid / 5, oo = tid - ss * 5;
        int ag = agents[sb + ss];
        const float* W = agw + (ag * 5 + oo) * 64;
        const float* h = h2S + ss * 64;
        float a = agb[ag * 5 + oo];
#pragma unroll
        for (int k = 0; k < 64; k++) a += W[k] * h[k];
        logS[ss * 8 + oo] = a;
    }
    __syncthreads();
    if (tid < 8) {
        float m = -1e30f;
        for (int i = 0; i < 5; i++) m = fmaxf(m, logS[tid * 8 + i]);
        float e[5], sum = 0.f;
        for (int i = 0; i < 5; i++) { e[i] = expf(logS[tid * 8 + i] - m); sum += e[i]; }
        float inv = 1.f / sum;
        for (int i = 0; i < 5; i++) out[(sb + tid) * 5 + i] = e[i] * inv;
    }
}

// ---------------- launch ----------------
extern "C" void kernel_launch(void* const* d_in, const int* in_sizes, int n_in,
                              void* d_out, int out_size) {
    const float* states = (const float*)d_in[0];
    const float* scores = (const float*)d_in[1];
    const float* times  = (const float*)d_in[2];
    const int*   agents = (const int*)d_in[3];
    const float* c1w = (const float*)d_in[4];
    const float* c1b = (const float*)d_in[5];
    const float* c2w = (const float*)d_in[6];
    const float* c2b = (const float*)d_in[7];
    const float* c3w = (const float*)d_in[8];
    const float* c3b = (const float*)d_in[9];
    const float* c4w = (const float*)d_in[10];
    const float* c4b = (const float*)d_in[11];
    const float* l1w = (const float*)d_in[12];
    const float* l1b = (const float*)d_in[13];
    const float* l2w = (const float*)d_in[14];
    const float* l2b = (const float*)d_in[15];
    const float* agw = (const float*)d_in[16];
    const float* agb = (const float*)d_in[17];
    float* out = (float*)d_out;

    cudaFuncSetAttribute(k_convA, cudaFuncAttributeMaxDynamicSharedMemorySize, SMEM_A);
    cudaFuncSetAttribute(k_conv3, cudaFuncAttributeMaxDynamicSharedMemorySize, SMEM_C3);
    cudaFuncSetAttribute(k_conv4, cudaFuncAttributeMaxDynamicSharedMemorySize, SMEM_C4);
    cudaFuncSetAttribute(k_mlp, cudaFuncAttributeMaxDynamicSharedMemorySize, SMEM_M);

    k_compose<<<3, 1024>>>(c1w, c1b, c2w, c2b);
    k_convA<<<dim3(5, 1024), 512, SMEM_A>>>(states);
    k_conv3<<<dim3(2, 1024), 512, SMEM_C3>>>(c3w, c3b);
    k_conv4<<<dim3(2, 1024), 512, SMEM_C4>>>(c4w, c4b);
    k_mlp<<<256, 512, SMEM_M>>>(scores, times, agents, l1w, l1b, l2w, l2b, agw, agb, out);
}